// round 1
// baseline (speedup 1.0000x reference)
#include <cuda_runtime.h>
#include <cstdint>

#define BB 16
#define CC 256
#define LLL 2048
#define RR 32768          // BB*LLL rows
#define NE 8192           // codebook size
#define ZN 8388608        // BB*CC*LLL
#define LOSS_OFF ZN
#define IND_OFF (ZN + 1)

// ---------------- scratch (device globals; no allocation allowed) ----------
__device__ float g_ctT[CC * NE];   // codebook transposed, k-major [256][8192]
__device__ float g_e2[NE];
__device__ float g_z2[RR];
__device__ float g_pd[2 * RR];
__device__ int   g_pi[2 * RR];
__device__ int   g_inds[RR];
__device__ double g_loss;

// ---------------- f32x2 packed FMA helpers (sm_100+) -----------------------
static __device__ __forceinline__ unsigned long long pack2(float x, float y) {
    unsigned long long r;
    asm("mov.b64 %0, {%1,%2};" : "=l"(r) : "f"(x), "f"(y));
    return r;
}
static __device__ __forceinline__ void unpack2(unsigned long long v, float& x, float& y) {
    asm("mov.b64 {%0,%1}, %2;" : "=f"(x), "=f"(y) : "l"(v));
}
static __device__ __forceinline__ void fma2(unsigned long long& c,
                                            unsigned long long a,
                                            unsigned long long b) {
    asm("fma.rn.f32x2 %0, %1, %2, %0;" : "+l"(c) : "l"(a), "l"(b));
}

// ---------------- codebook transpose: [8192][256] -> [256][8192] -----------
__global__ void k_transpose(const float* __restrict__ cb) {
    __shared__ float t[32][33];
    int n0 = blockIdx.x * 32, k0 = blockIdx.y * 32;
    int tx = threadIdx.x, ty = threadIdx.y;
#pragma unroll
    for (int j = 0; j < 4; j++)
        t[ty + j * 8][tx] = cb[(n0 + ty + j * 8) * CC + (k0 + tx)];
    __syncthreads();
#pragma unroll
    for (int j = 0; j < 4; j++)
        g_ctT[(k0 + ty + j * 8) * NE + (n0 + tx)] = t[tx][ty + j * 8];
}

// ---------------- e2[n] = sum_k cb[n][k]^2 ---------------------------------
__global__ void k_e2(const float* __restrict__ cb) {
    int row = blockIdx.x * 8 + (threadIdx.x >> 5);
    int lane = threadIdx.x & 31;
    const float* p = cb + row * CC;
    float s = 0.f;
#pragma unroll
    for (int i = 0; i < 8; i++) { float v = p[lane + i * 32]; s = fmaf(v, v, s); }
#pragma unroll
    for (int o = 16; o; o >>= 1) s += __shfl_down_sync(0xffffffffu, s, o);
    if (lane == 0) g_e2[row] = s;
}

// ---------------- z2[r] = sum_c z[b][c][l]^2  (r = b*2048 + l) -------------
__global__ void k_z2(const float* __restrict__ z) {
    int r = blockIdx.x * 256 + threadIdx.x;
    const float* p = z + (size_t)(r >> 11) * (CC * LLL) + (r & 2047);
    float s0 = 0.f, s1 = 0.f, s2 = 0.f, s3 = 0.f;
#pragma unroll 8
    for (int c = 0; c < CC; c += 4) {
        float a = p[(c + 0) * LLL]; s0 = fmaf(a, a, s0);
        float b = p[(c + 1) * LLL]; s1 = fmaf(b, b, s1);
        float d = p[(c + 2) * LLL]; s2 = fmaf(d, d, s2);
        float e = p[(c + 3) * LLL]; s3 = fmaf(e, e, s3);
    }
    g_z2[r] = (s0 + s1) + (s2 + s3);
    if (r == 0) g_loss = 0.0;
}

// ---------------- fused distance + argmin ----------------------------------
// grid (512, 2): blockIdx.x = 64-row M tile, blockIdx.y = N half (4096 codes)
// block: 128 threads (tx 0..15 over N, ty 0..7 over M), 8x8 per-thread tile.
// smem: As[256][64] (full-K A tile) + double-buffered Bs[2][16][128].
#define SMEM_MAIN ((CC * 64 + 2 * 16 * 128) * 4)

__global__ __launch_bounds__(128, 2)
void k_main(const float* __restrict__ z) {
    extern __shared__ float smem[];
    float* As = smem;               // 16384 floats
    float* Bs = smem + CC * 64;     // 4096 floats (2 buffers)

    const int tid = threadIdx.x;
    const int tx = tid & 15, ty = tid >> 4;
    const int m0 = blockIdx.x * 64;
    const int ns = blockIdx.y;
    const int b  = m0 >> 11;
    const int l0 = m0 & 2047;
    const float* zb = z + (size_t)b * (CC * LLL) + l0;

    // load A tile (64 rows x full K=256), k-major: As[k][m]
    for (int i = tid; i < (CC * 64) / 4; i += 128) {
        int k = i >> 4; int m4 = (i & 15) << 2;
        *(float4*)(As + k * 64 + m4) = *(const float4*)(zb + k * LLL + m4);
    }
    float z2r[8];
#pragma unroll
    for (int i = 0; i < 8; i++) z2r[i] = g_z2[m0 + ty * 8 + i];
    float bd[8]; int bi[8];
#pragma unroll
    for (int i = 0; i < 8; i++) { bd[i] = __int_as_float(0x7f800000); bi[i] = 0; }
    __syncthreads();

    for (int nt = 0; nt < 32; nt++) {
        const int nb = ns * 4096 + nt * 128;
        unsigned long long acc[8][4];
#pragma unroll
        for (int i = 0; i < 8; i++)
#pragma unroll
            for (int j = 0; j < 4; j++) acc[i][j] = 0ull;

        // prefetch chunk 0 into registers
        float4 st[4];
        {
            const float* src = g_ctT + nb;
#pragma unroll
            for (int q = 0; q < 4; q++) {
                int i = tid + q * 128; int kk = i >> 5; int n4 = (i & 31) << 2;
                st[q] = *(const float4*)(src + kk * NE + n4);
            }
        }
        for (int kc = 0; kc < 16; kc++) {
            float* Bw = Bs + (kc & 1) * (16 * 128);
#pragma unroll
            for (int q = 0; q < 4; q++) {
                int i = tid + q * 128; int kk = i >> 5; int n4 = (i & 31) << 2;
                *(float4*)(Bw + kk * 128 + n4) = st[q];
            }
            if (kc < 15) {
                const float* src = g_ctT + (size_t)(kc + 1) * 16 * NE + nb;
#pragma unroll
                for (int q = 0; q < 4; q++) {
                    int i = tid + q * 128; int kk = i >> 5; int n4 = (i & 31) << 2;
                    st[q] = *(const float4*)(src + kk * NE + n4);
                }
            }
            __syncthreads();
            const float* Br = Bw;
#pragma unroll 4
            for (int kk = 0; kk < 16; kk++) {
                const float* arow = As + (kc * 16 + kk) * 64 + ty * 8;
                float4 a0 = *(const float4*)(arow);
                float4 a1 = *(const float4*)(arow + 4);
                const ulonglong2* bp = (const ulonglong2*)(Br + kk * 128 + tx * 8);
                ulonglong2 bv0 = bp[0];
                ulonglong2 bv1 = bp[1];
                float am[8] = {a0.x, a0.y, a0.z, a0.w, a1.x, a1.y, a1.z, a1.w};
#pragma unroll
                for (int i = 0; i < 8; i++) {
                    unsigned long long aa = pack2(am[i], am[i]);
                    fma2(acc[i][0], aa, bv0.x);
                    fma2(acc[i][1], aa, bv0.y);
                    fma2(acc[i][2], aa, bv1.x);
                    fma2(acc[i][3], aa, bv1.y);
                }
            }
        }
        // epilogue: d = (z2 + e2) - 2*dot, fp32-rounded like the reference
        float e2v[8];
#pragma unroll
        for (int j = 0; j < 8; j++) e2v[j] = g_e2[nb + tx * 8 + j];
#pragma unroll
        for (int i = 0; i < 8; i++) {
#pragma unroll
            for (int j2 = 0; j2 < 4; j2++) {
                float s0, s1; unpack2(acc[i][j2], s0, s1);
                int n = nb + tx * 8 + j2 * 2;
                float d0 = __fmaf_rn(-2.f, s0, z2r[i] + e2v[j2 * 2 + 0]);
                float d1 = __fmaf_rn(-2.f, s1, z2r[i] + e2v[j2 * 2 + 1]);
                if (d0 < bd[i]) { bd[i] = d0; bi[i] = n; }
                if (d1 < bd[i]) { bd[i] = d1; bi[i] = n + 1; }
            }
        }
    }

    // cross-thread (tx) reduction per row, tie -> lowest index
    __syncthreads();
    float* redf = Bs;
    int*   redi = (int*)(Bs + 1024);
#pragma unroll
    for (int i = 0; i < 8; i++) {
        redf[(ty * 8 + i) * 16 + tx] = bd[i];
        redi[(ty * 8 + i) * 16 + tx] = bi[i];
    }
    __syncthreads();
    if (tid < 64) {
        float best = redf[tid * 16]; int besti = redi[tid * 16];
#pragma unroll
        for (int t = 1; t < 16; t++) {
            float d = redf[tid * 16 + t]; int ii = redi[tid * 16 + t];
            if (d < best || (d == best && ii < besti)) { best = d; besti = ii; }
        }
        g_pd[ns * RR + m0 + tid] = best;
        g_pi[ns * RR + m0 + tid] = besti;
    }
}

// ---------------- merge the two N-halves, emit inds ------------------------
__global__ void k_merge(float* __restrict__ out) {
    int r = blockIdx.x * 256 + threadIdx.x;
    float d0 = g_pd[r], d1 = g_pd[RR + r];
    int   i0 = g_pi[r], i1 = g_pi[RR + r];
    int best = (d1 < d0 || (d1 == d0 && i1 < i0)) ? i1 : i0;
    g_inds[r] = best;
    out[IND_OFF + r] = (float)best;
}

// ---------------- z_q gather + loss accumulation ---------------------------
__global__ void k_zq(const float* __restrict__ z, const float* __restrict__ cb,
                     float* __restrict__ out) {
    int e = blockIdx.x * 256 + threadIdx.x;
    int l = e & 2047;
    int c = (e >> 11) & 255;
    int b = e >> 19;
    int r = (b << 11) | l;
    float v = cb[g_inds[r] * CC + c];
    out[e] = v;
    float diff = v - z[e];
    double d2 = (double)diff * (double)diff;
#pragma unroll
    for (int o = 16; o; o >>= 1)
        d2 += __shfl_down_sync(0xffffffffu, d2, o);
    __shared__ double ws[8];
    if ((threadIdx.x & 31) == 0) ws[threadIdx.x >> 5] = d2;
    __syncthreads();
    if (threadIdx.x == 0) {
        double s = 0.0;
#pragma unroll
        for (int w = 0; w < 8; w++) s += ws[w];
        atomicAdd(&g_loss, s);
    }
}

__global__ void k_fin(float* __restrict__ out) {
    double m = g_loss / (double)ZN;
    out[LOSS_OFF] = (float)(0.1 * m + m);
}

// ---------------- launch ----------------------------------------------------
extern "C" void kernel_launch(void* const* d_in, const int* in_sizes, int n_in,
                              void* d_out, int out_size) {
    const float* z  = (const float*)d_in[0];
    const float* cb = (const float*)d_in[1];
    if (n_in >= 2 && in_sizes[0] == NE * CC) {  // defensive: inputs swapped
        z  = (const float*)d_in[1];
        cb = (const float*)d_in[0];
    }
    float* out = (float*)d_out;

    cudaFuncSetAttribute(k_main, cudaFuncAttributeMaxDynamicSharedMemorySize, SMEM_MAIN);

    k_transpose<<<dim3(NE / 32, CC / 32), dim3(32, 8)>>>(cb);
    k_e2<<<NE / 8, 256>>>(cb);
    k_z2<<<RR / 256, 256>>>(z);
    k_main<<<dim3(RR / 64, 2), 128, SMEM_MAIN>>>(z);
    k_merge<<<RR / 256, 256>>>(out);
    k_zq<<<ZN / 256, 256>>>(z, cb, out);
    k_fin<<<1, 1>>>(out);
}

// round 2
// speedup vs baseline: 1.0010x; 1.0010x over previous
#include <cuda_runtime.h>
#include <cstdint>

#define BB 16
#define CC 256
#define LLL 2048
#define RR 32768          // BB*LLL rows
#define NE 8192           // codebook size
#define ZN 8388608        // BB*CC*LLL
#define LOSS_OFF ZN
#define IND_OFF (ZN + 1)

// ---------------- scratch (device globals; no allocation allowed) ----------
__device__ float g_ctT[CC * NE];   // codebook transposed, k-major [256][8192]
__device__ float g_e2[NE];
__device__ float g_z2[RR];
__device__ float g_pd[2 * RR];
__device__ int   g_pi[2 * RR];
__device__ int   g_inds[RR];
__device__ double g_loss;

// ---------------- f32x2 packed FMA helpers (sm_100+) -----------------------
static __device__ __forceinline__ unsigned long long pack2(float x, float y) {
    unsigned long long r;
    asm("mov.b64 %0, {%1,%2};" : "=l"(r) : "f"(x), "f"(y));
    return r;
}
static __device__ __forceinline__ void unpack2(unsigned long long v, float& x, float& y) {
    asm("mov.b64 {%0,%1}, %2;" : "=f"(x), "=f"(y) : "l"(v));
}
static __device__ __forceinline__ void fma2(unsigned long long& c,
                                            unsigned long long a,
                                            unsigned long long b) {
    asm("fma.rn.f32x2 %0, %1, %2, %0;" : "+l"(c) : "l"(a), "l"(b));
}

// ---------------- codebook transpose: [8192][256] -> [256][8192] -----------
__global__ void k_transpose(const float* __restrict__ cb) {
    __shared__ float t[32][33];
    int n0 = blockIdx.x * 32, k0 = blockIdx.y * 32;
    int tx = threadIdx.x, ty = threadIdx.y;
#pragma unroll
    for (int j = 0; j < 4; j++)
        t[ty + j * 8][tx] = cb[(n0 + ty + j * 8) * CC + (k0 + tx)];
    __syncthreads();
#pragma unroll
    for (int j = 0; j < 4; j++)
        g_ctT[(k0 + ty + j * 8) * NE + (n0 + tx)] = t[tx][ty + j * 8];
}

// ---------------- e2[n] = sum_k cb[n][k]^2 ---------------------------------
__global__ void k_e2(const float* __restrict__ cb) {
    int row = blockIdx.x * 8 + (threadIdx.x >> 5);
    int lane = threadIdx.x & 31;
    const float* p = cb + row * CC;
    float s = 0.f;
#pragma unroll
    for (int i = 0; i < 8; i++) { float v = p[lane + i * 32]; s = fmaf(v, v, s); }
#pragma unroll
    for (int o = 16; o; o >>= 1) s += __shfl_down_sync(0xffffffffu, s, o);
    if (lane == 0) g_e2[row] = s;
}

// ---------------- z2[r] = sum_c z[b][c][l]^2  (r = b*2048 + l) -------------
__global__ void k_z2(const float* __restrict__ z) {
    int r = blockIdx.x * 256 + threadIdx.x;
    const float* p = z + (size_t)(r >> 11) * (CC * LLL) + (r & 2047);
    float s0 = 0.f, s1 = 0.f, s2 = 0.f, s3 = 0.f;
#pragma unroll 8
    for (int c = 0; c < CC; c += 4) {
        float a = p[(c + 0) * LLL]; s0 = fmaf(a, a, s0);
        float b = p[(c + 1) * LLL]; s1 = fmaf(b, b, s1);
        float d = p[(c + 2) * LLL]; s2 = fmaf(d, d, s2);
        float e = p[(c + 3) * LLL]; s3 = fmaf(e, e, s3);
    }
    g_z2[r] = (s0 + s1) + (s2 + s3);
    if (r == 0) g_loss = 0.0;
}

// ---------------- fused distance + argmin ----------------------------------
// grid (512, 2): blockIdx.x = 64-row M tile, blockIdx.y = N half (4096 codes)
// block: 128 threads (tx 0..15 over N, ty 0..7 over M), 8x8 per-thread tile.
// smem: As[256][64] (full-K A tile) + double-buffered Bs[2][16][128].
#define SMEM_MAIN ((CC * 64 + 2 * 16 * 128) * 4)

__global__ __launch_bounds__(128, 2)
void k_main(const float* __restrict__ z) {
    extern __shared__ float smem[];
    float* As = smem;               // 16384 floats
    float* Bs = smem + CC * 64;     // 4096 floats (2 buffers)

    const int tid = threadIdx.x;
    const int tx = tid & 15, ty = tid >> 4;
    const int m0 = blockIdx.x * 64;
    const int ns = blockIdx.y;
    const int b  = m0 >> 11;
    const int l0 = m0 & 2047;
    const float* zb = z + (size_t)b * (CC * LLL) + l0;

    // load A tile (64 rows x full K=256), k-major: As[k][m]
    for (int i = tid; i < (CC * 64) / 4; i += 128) {
        int k = i >> 4; int m4 = (i & 15) << 2;
        *(float4*)(As + k * 64 + m4) = *(const float4*)(zb + k * LLL + m4);
    }
    float z2r[8];
#pragma unroll
    for (int i = 0; i < 8; i++) z2r[i] = g_z2[m0 + ty * 8 + i];
    float bd[8]; int bi[8];
#pragma unroll
    for (int i = 0; i < 8; i++) { bd[i] = __int_as_float(0x7f800000); bi[i] = 0; }
    __syncthreads();

    for (int nt = 0; nt < 32; nt++) {
        const int nb = ns * 4096 + nt * 128;
        unsigned long long acc[8][4];
#pragma unroll
        for (int i = 0; i < 8; i++)
#pragma unroll
            for (int j = 0; j < 4; j++) acc[i][j] = 0ull;

        // prefetch chunk 0 into registers
        float4 st[4];
        {
            const float* src = g_ctT + nb;
#pragma unroll
            for (int q = 0; q < 4; q++) {
                int i = tid + q * 128; int kk = i >> 5; int n4 = (i & 31) << 2;
                st[q] = *(const float4*)(src + kk * NE + n4);
            }
        }
        for (int kc = 0; kc < 16; kc++) {
            float* Bw = Bs + (kc & 1) * (16 * 128);
#pragma unroll
            for (int q = 0; q < 4; q++) {
                int i = tid + q * 128; int kk = i >> 5; int n4 = (i & 31) << 2;
                *(float4*)(Bw + kk * 128 + n4) = st[q];
            }
            if (kc < 15) {
                const float* src = g_ctT + (size_t)(kc + 1) * 16 * NE + nb;
#pragma unroll
                for (int q = 0; q < 4; q++) {
                    int i = tid + q * 128; int kk = i >> 5; int n4 = (i & 31) << 2;
                    st[q] = *(const float4*)(src + kk * NE + n4);
                }
            }
            __syncthreads();
            const float* Br = Bw;
#pragma unroll 4
            for (int kk = 0; kk < 16; kk++) {
                const float* arow = As + (kc * 16 + kk) * 64 + ty * 8;
                float4 a0 = *(const float4*)(arow);
                float4 a1 = *(const float4*)(arow + 4);
                const ulonglong2* bp = (const ulonglong2*)(Br + kk * 128 + tx * 8);
                ulonglong2 bv0 = bp[0];
                ulonglong2 bv1 = bp[1];
                float am[8] = {a0.x, a0.y, a0.z, a0.w, a1.x, a1.y, a1.z, a1.w};
#pragma unroll
                for (int i = 0; i < 8; i++) {
                    unsigned long long aa = pack2(am[i], am[i]);
                    fma2(acc[i][0], aa, bv0.x);
                    fma2(acc[i][1], aa, bv0.y);
                    fma2(acc[i][2], aa, bv1.x);
                    fma2(acc[i][3], aa, bv1.y);
                }
            }
        }
        // epilogue: d = (z2 + e2) - 2*dot, fp32-rounded like the reference
        float e2v[8];
#pragma unroll
        for (int j = 0; j < 8; j++) e2v[j] = g_e2[nb + tx * 8 + j];
#pragma unroll
        for (int i = 0; i < 8; i++) {
#pragma unroll
            for (int j2 = 0; j2 < 4; j2++) {
                float s0, s1; unpack2(acc[i][j2], s0, s1);
                int n = nb + tx * 8 + j2 * 2;
                float d0 = __fmaf_rn(-2.f, s0, z2r[i] + e2v[j2 * 2 + 0]);
                float d1 = __fmaf_rn(-2.f, s1, z2r[i] + e2v[j2 * 2 + 1]);
                if (d0 < bd[i]) { bd[i] = d0; bi[i] = n; }
                if (d1 < bd[i]) { bd[i] = d1; bi[i] = n + 1; }
            }
        }
    }

    // cross-thread (tx) reduction per row, tie -> lowest index
    __syncthreads();
    float* redf = Bs;
    int*   redi = (int*)(Bs + 1024);
#pragma unroll
    for (int i = 0; i < 8; i++) {
        redf[(ty * 8 + i) * 16 + tx] = bd[i];
        redi[(ty * 8 + i) * 16 + tx] = bi[i];
    }
    __syncthreads();
    if (tid < 64) {
        float best = redf[tid * 16]; int besti = redi[tid * 16];
#pragma unroll
        for (int t = 1; t < 16; t++) {
            float d = redf[tid * 16 + t]; int ii = redi[tid * 16 + t];
            if (d < best || (d == best && ii < besti)) { best = d; besti = ii; }
        }
        g_pd[ns * RR + m0 + tid] = best;
        g_pi[ns * RR + m0 + tid] = besti;
    }
}

// ---------------- merge the two N-halves, emit inds ------------------------
__global__ void k_merge(float* __restrict__ out) {
    int r = blockIdx.x * 256 + threadIdx.x;
    float d0 = g_pd[r], d1 = g_pd[RR + r];
    int   i0 = g_pi[r], i1 = g_pi[RR + r];
    int best = (d1 < d0 || (d1 == d0 && i1 < i0)) ? i1 : i0;
    g_inds[r] = best;
    out[IND_OFF + r] = (float)best;
}

// ---------------- z_q gather + loss accumulation ---------------------------
__global__ void k_zq(const float* __restrict__ z, const float* __restrict__ cb,
                     float* __restrict__ out) {
    int e = blockIdx.x * 256 + threadIdx.x;
    int l = e & 2047;
    int c = (e >> 11) & 255;
    int b = e >> 19;
    int r = (b << 11) | l;
    float v = cb[g_inds[r] * CC + c];
    out[e] = v;
    float diff = v - z[e];
    double d2 = (double)diff * (double)diff;
#pragma unroll
    for (int o = 16; o; o >>= 1)
        d2 += __shfl_down_sync(0xffffffffu, d2, o);
    __shared__ double ws[8];
    if ((threadIdx.x & 31) == 0) ws[threadIdx.x >> 5] = d2;
    __syncthreads();
    if (threadIdx.x == 0) {
        double s = 0.0;
#pragma unroll
        for (int w = 0; w < 8; w++) s += ws[w];
        atomicAdd(&g_loss, s);
    }
}

__global__ void k_fin(float* __restrict__ out) {
    double m = g_loss / (double)ZN;
    out[LOSS_OFF] = (float)(0.1 * m + m);
}

// ---------------- launch ----------------------------------------------------
extern "C" void kernel_launch(void* const* d_in, const int* in_sizes, int n_in,
                              void* d_out, int out_size) {
    const float* z  = (const float*)d_in[0];
    const float* cb = (const float*)d_in[1];
    if (n_in >= 2 && in_sizes[0] == NE * CC) {  // defensive: inputs swapped
        z  = (const float*)d_in[1];
        cb = (const float*)d_in[0];
    }
    float* out = (float*)d_out;

    cudaFuncSetAttribute(k_main, cudaFuncAttributeMaxDynamicSharedMemorySize, SMEM_MAIN);

    k_transpose<<<dim3(NE / 32, CC / 32), dim3(32, 8)>>>(cb);
    k_e2<<<NE / 8, 256>>>(cb);
    k_z2<<<RR / 256, 256>>>(z);
    k_main<<<dim3(RR / 64, 2), 128, SMEM_MAIN>>>(z);
    k_merge<<<RR / 256, 256>>>(out);
    k_zq<<<ZN / 256, 256>>>(z, cb, out);
    k_fin<<<1, 1>>>(out);
}

// round 4
// speedup vs baseline: 2.7183x; 2.7157x over previous
#include <cuda_runtime.h>
#include <cuda_fp16.h>
#include <cstdint>
#include <cstddef>

#define CC 256
#define LLL 2048
#define RR 32768
#define NE 8192
#define ZN 8388608
#define LOSS_OFF ZN
#define IND_OFF (ZN + 1)
#define NTILE 64            // 8192 / 128
#define KEEP 4
#define NCAND (NTILE * KEEP)   // 256
#define MARGIN 2e-4f
#define DSCALE (-4.8828125e-4f)  // -2 / 4096

__device__ float  g_zt[RR * CC];        // exact transposed z rows
__device__ __half g_Ah[RR * CC];        // fp16 z rows
__device__ __half g_Bh[NE * CC];        // fp16 codebook * 4096
__device__ float  g_cd[(size_t)RR * NCAND];
__device__ int    g_ci[(size_t)RR * NCAND];
__device__ float  g_z2[RR];
__device__ int    g_inds[RR];
__device__ double g_loss;

static __device__ __forceinline__ uint32_t smem_u32(const void* p) {
    uint32_t a;
    asm("{ .reg .u64 t; cvta.to.shared.u64 t, %1; cvt.u32.u64 %0, t; }" : "=r"(a) : "l"(p));
    return a;
}
static __device__ __forceinline__ void cpa16(uint32_t dst, const void* src) {
    asm volatile("cp.async.cg.shared.global [%0], [%1], 16;" :: "r"(dst), "l"(src) : "memory");
}
#define CP_COMMIT() asm volatile("cp.async.commit_group;" ::: "memory")
#define CP_WAIT2()  asm volatile("cp.async.wait_group 2;" ::: "memory")

#define LDSM4(r, a) \
    asm volatile("ldmatrix.sync.aligned.m8n8.x4.shared.b16 {%0,%1,%2,%3}, [%4];" \
                 : "=r"((r)[0]), "=r"((r)[1]), "=r"((r)[2]), "=r"((r)[3]) : "r"(a))

#define MMA16816(c, a, b0, b1) \
    asm volatile("mma.sync.aligned.m16n8k16.row.col.f32.f16.f16.f32 " \
                 "{%0,%1,%2,%3}, {%4,%5,%6,%7}, {%8,%9}, {%0,%1,%2,%3};" \
                 : "+f"((c)[0]), "+f"((c)[1]), "+f"((c)[2]), "+f"((c)[3]) \
                 : "r"((a)[0]), "r"((a)[1]), "r"((a)[2]), "r"((a)[3]), "r"(b0), "r"(b1))

// ---------------- prep: transpose z -> zt fp32 + Ah fp16 -------------------
__global__ void k_prepz(const float* __restrict__ z) {
    __shared__ float t[32][33];
    int r0 = blockIdx.x * 32, c0 = blockIdx.y * 32;
    int b = r0 >> 11, l0 = r0 & 2047;
    int tx = threadIdx.x, ty = threadIdx.y;
    const float* zb = z + (size_t)b * CC * LLL;
#pragma unroll
    for (int j = 0; j < 4; j++)
        t[ty + j * 8][tx] = zb[(size_t)(c0 + ty + j * 8) * LLL + l0 + tx];
    __syncthreads();
#pragma unroll
    for (int j = 0; j < 4; j++) {
        int r = r0 + ty + j * 8, c = c0 + tx;
        float v = t[tx][ty + j * 8];
        g_zt[(size_t)r * CC + c] = v;
        g_Ah[(size_t)r * CC + c] = __float2half_rn(v);
    }
}

__global__ void k_prepcb(const float* __restrict__ cb) {
    int i = blockIdx.x * 256 + threadIdx.x;
    g_Bh[i] = __float2half_rn(cb[i] * 4096.0f);
}

__global__ void k_z2(const float* __restrict__ z) {
    int r = blockIdx.x * 256 + threadIdx.x;
    const float* p = z + (size_t)(r >> 11) * (CC * LLL) + (r & 2047);
    float s0 = 0.f, s1 = 0.f, s2 = 0.f, s3 = 0.f;
#pragma unroll 8
    for (int c = 0; c < CC; c += 4) {
        float a = p[(c + 0) * LLL]; s0 = fmaf(a, a, s0);
        float b = p[(c + 1) * LLL]; s1 = fmaf(b, b, s1);
        float d = p[(c + 2) * LLL]; s2 = fmaf(d, d, s2);
        float e = p[(c + 3) * LLL]; s3 = fmaf(e, e, s3);
    }
    g_z2[r] = (s0 + s1) + (s2 + s3);
    if (r == 0) g_loss = 0.0;
}

// ---------------- phase 1: fp16 mma.sync GEMM + per-tile top-4 -------------
// CTA 256 thr = 8 warps (wm 0..3 x wn 0..1). Tile M=128,N=128; K staged by 16.
// smem stage: A 128 rows x 48B (16 fp16 + pad) + B same = 12288 B; 4 stages.
#define STAGE_B 12288
#define SMEM_MMA (4 * STAGE_B)

__global__ __launch_bounds__(256, 2) void k_mma() {
    extern __shared__ char smem[];
    const uint32_t sb = smem_u32(smem);
    const int tid = threadIdx.x, lane = tid & 31, wid = tid >> 5;
    const int wm = wid & 3, wn = wid >> 2;
    const int m0 = blockIdx.x * 128, n0 = blockIdx.y * 128;

    const int lrow = tid >> 1, lch = tid & 1;
    const __half* Ag = g_Ah + (size_t)(m0 + lrow) * CC + lch * 8;
    const __half* Bg = g_Bh + (size_t)(n0 + lrow) * CC + lch * 8;
    const uint32_t dstA = sb + lrow * 48 + lch * 16;
    const uint32_t dstB = dstA + 6144;

#pragma unroll
    for (int s = 0; s < 3; s++) {
        cpa16(dstA + s * STAGE_B, Ag + s * 16);
        cpa16(dstB + s * STAGE_B, Bg + s * 16);
        CP_COMMIT();
    }

    float acc[2][8][4];
#pragma unroll
    for (int i = 0; i < 2; i++)
#pragma unroll
        for (int j = 0; j < 8; j++)
#pragma unroll
            for (int k = 0; k < 4; k++) acc[i][j][k] = 0.f;

    // ldmatrix lane addressing: quad q=lane>>3 selects 8x8 tile
    const int q = lane >> 3, i8 = lane & 7;
    const uint32_t aoff = (uint32_t)((wm * 32 + i8 + (q & 1) * 8) * 48 + (q >> 1) * 16);
    const uint32_t boff = (uint32_t)((wn * 64 + i8 + (q & 1) * 8) * 48 + (q >> 1) * 16) + 6144;

    for (int ks = 0; ks < 16; ks++) {
        CP_WAIT2();
        __syncthreads();
        const uint32_t base = sb + (ks & 3) * STAGE_B;
        uint32_t a[2][4], b[4][4];
        LDSM4(a[0], base + aoff);
        LDSM4(a[1], base + aoff + 16 * 48);
#pragma unroll
        for (int bt = 0; bt < 4; bt++) LDSM4(b[bt], base + boff + bt * 16 * 48);
#pragma unroll
        for (int mt = 0; mt < 2; mt++)
#pragma unroll
            for (int nf = 0; nf < 8; nf++) {
                // b-frag for n-half p of tile bt: regs {r[p], r[p+2]}
                int bt = nf >> 1, p = nf & 1;
                MMA16816(acc[mt][nf], a[mt], b[bt][p], b[bt][p + 2]);
            }
        if (ks < 13) {
            int s2 = ks + 3;
            cpa16(dstA + (s2 & 3) * STAGE_B, Ag + s2 * 16);
            cpa16(dstB + (s2 & 3) * STAGE_B, Bg + s2 * 16);
        }
        CP_COMMIT();  // unconditional (possibly empty) keeps group counting simple
    }
    __syncthreads();

    // epilogue: per-row top-4 (largest dot) within this 128-col tile
    float* ep_d = (float*)smem;               // [128][32]
    int*   ep_i = (int*)(smem + 16384);       // [128][32]
#pragma unroll
    for (int mt = 0; mt < 2; mt++)
#pragma unroll
        for (int half = 0; half < 2; half++) {
            int rl = wm * 32 + mt * 16 + (lane >> 2) + half * 8;
            float tv[KEEP]; int tc[KEEP];
#pragma unroll
            for (int j = 0; j < KEEP; j++) { tv[j] = -__int_as_float(0x7f800000); tc[j] = 0; }
#pragma unroll
            for (int nf = 0; nf < 8; nf++)
#pragma unroll
                for (int par = 0; par < 2; par++) {
                    float c = acc[mt][nf][half * 2 + par];
                    if (c > tv[KEEP - 1]) {
                        int col = wn * 64 + nf * 8 + (lane & 3) * 2 + par;
                        tv[KEEP - 1] = c; tc[KEEP - 1] = col;
#pragma unroll
                        for (int j = KEEP - 1; j > 0; j--)
                            if (tv[j] > tv[j - 1]) {
                                float tf = tv[j]; tv[j] = tv[j - 1]; tv[j - 1] = tf;
                                int tu = tc[j]; tc[j] = tc[j - 1]; tc[j - 1] = tu;
                            }
                    }
                }
            int slot = rl * 32 + (wn * 4 + (lane & 3)) * 4;
#pragma unroll
            for (int j = 0; j < KEEP; j++) {
                ep_d[slot + j] = DSCALE * tv[j];   // -2*dot (approx); -inf -> +inf
                ep_i[slot + j] = tc[j];
            }
        }
    __syncthreads();
    if (tid < 128) {
        float* pd = ep_d + tid * 32;
        int*   pi = ep_i + tid * 32;
        size_t out = (size_t)(m0 + tid) * NCAND + blockIdx.y * KEEP;
#pragma unroll
        for (int j = 0; j < KEEP; j++) {
            float bm = pd[0]; int bk = 0;
#pragma unroll 8
            for (int t = 1; t < 32; t++)
                if (pd[t] < bm) { bm = pd[t]; bk = t; }
            g_cd[out + j] = bm;
            g_ci[out + j] = n0 + pi[bk];
            pd[bk] = __int_as_float(0x7f800000);
        }
    }
}

// ---------------- phase 2: margin filter + exact fp32 rescore --------------
__global__ void k_pick(const float* __restrict__ cb, float* __restrict__ out) {
    const int wid = threadIdx.x >> 5, lane = threadIdx.x & 31;
    const int r = blockIdx.x * 8 + wid;
    const float* cd = g_cd + (size_t)r * NCAND;
    const int*   ci = g_ci + (size_t)r * NCAND;
    float dv[8]; int iv[8];
    float mn = __int_as_float(0x7f800000);
#pragma unroll
    for (int j = 0; j < 8; j++) {
        dv[j] = cd[lane + j * 32]; iv[j] = ci[lane + j * 32];
        mn = fminf(mn, dv[j]);
    }
#pragma unroll
    for (int o = 16; o; o >>= 1) mn = fminf(mn, __shfl_xor_sync(0xffffffffu, mn, o));
    const float thr = mn + MARGIN;

    float zr[8];
    const float* zt = g_zt + (size_t)r * CC;
#pragma unroll
    for (int k = 0; k < 8; k++) zr[k] = zt[lane + k * 32];
    const float z2r = g_z2[r];

    float best = __int_as_float(0x7f800000); int besti = 0x7fffffff;
#pragma unroll
    for (int j = 0; j < 8; j++) {
        unsigned m = __ballot_sync(0xffffffffu, dv[j] <= thr);
        while (m) {
            int src = __ffs(m) - 1; m &= m - 1;
            int n = __shfl_sync(0xffffffffu, iv[j], src);
            const float* cbn = cb + (size_t)n * CC;
            float s = 0.f;
#pragma unroll
            for (int k = 0; k < 8; k++) s = fmaf(zr[k], cbn[lane + k * 32], s);
#pragma unroll
            for (int o = 16; o; o >>= 1) s += __shfl_xor_sync(0xffffffffu, s, o);
            float dx = __fmaf_rn(-2.f, s, z2r);
            if (dx < best || (dx == best && n < besti)) { best = dx; besti = n; }
        }
    }
    if (lane == 0) { g_inds[r] = besti; out[IND_OFF + r] = (float)besti; }
}

// ---------------- z_q gather + loss ----------------------------------------
__global__ void k_zq(const float* __restrict__ z, const float* __restrict__ cb,
                     float* __restrict__ out) {
    int e = blockIdx.x * 256 + threadIdx.x;
    int l = e & 2047;
    int c = (e >> 11) & 255;
    int b = e >> 19;
    int r = (b << 11) | l;
    float v = cb[g_inds[r] * CC + c];
    out[e] = v;
    float diff = v - z[e];
    double d2 = (double)diff * (double)diff;
#pragma unroll
    for (int o = 16; o; o >>= 1) d2 += __shfl_down_sync(0xffffffffu, d2, o);
    __shared__ double ws[8];
    if ((threadIdx.x & 31) == 0) ws[threadIdx.x >> 5] = d2;
    __syncthreads();
    if (threadIdx.x == 0) {
        double s = 0.0;
#pragma unroll
        for (int w = 0; w < 8; w++) s += ws[w];
        atomicAdd(&g_loss, s);
    }
}

__global__ void k_fin(float* __restrict__ out) {
    double m = g_loss / (double)ZN;
    out[LOSS_OFF] = (float)(0.1 * m + m);
}

extern "C" void kernel_launch(void* const* d_in, const int* in_sizes, int n_in,
                              void* d_out, int out_size) {
    const float* z  = (const float*)d_in[0];
    const float* cb = (const float*)d_in[1];
    if (n_in >= 2 && in_sizes[0] == NE * CC) { z = (const float*)d_in[1]; cb = (const float*)d_in[0]; }
    float* out = (float*)d_out;

    cudaFuncSetAttribute(k_mma, cudaFuncAttributeMaxDynamicSharedMemorySize, SMEM_MMA);

    k_prepz<<<dim3(RR / 32, CC / 32), dim3(32, 8)>>>(z);
    k_prepcb<<<NE * CC / 256, 256>>>(cb);
    k_z2<<<RR / 256, 256>>>(z);
    k_mma<<<dim3(RR / 128, NE / 128), 256, SMEM_MMA>>>();
    k_pick<<<RR / 8, 256>>>(cb, out);
    k_zq<<<ZN / 256, 256>>>(z, cb, out);
    k_fin<<<1, 1>>>(out);
}

// round 5
// speedup vs baseline: 3.0084x; 1.1067x over previous
#include <cuda_runtime.h>
#include <cuda_fp16.h>
#include <cstdint>
#include <cstddef>

#define CC 256
#define LLL 2048
#define RR 32768
#define NE 8192
#define ZN 8388608
#define LOSS_OFF ZN
#define IND_OFF (ZN + 1)
#define NTILE 64
#define KEEP 4
#define NCAND (NTILE * KEEP)   // 256
#define MARGIN 2e-4f
#define DSCALE (-4.8828125e-4f)  // -2 / 4096

__device__ float  g_zt[RR * CC];
__device__ __half g_Ah[RR * CC];
__device__ __half g_Bh[NE * CC];
__device__ float  g_cd[(size_t)RR * NCAND];
__device__ int    g_ci[(size_t)RR * NCAND];
__device__ int    g_inds[RR];
__device__ double g_loss;

static __device__ __forceinline__ uint32_t smem_u32(const void* p) {
    uint32_t a;
    asm("{ .reg .u64 t; cvta.to.shared.u64 t, %1; cvt.u32.u64 %0, t; }" : "=r"(a) : "l"(p));
    return a;
}
static __device__ __forceinline__ void cpa16(uint32_t dst, const void* src) {
    asm volatile("cp.async.cg.shared.global [%0], [%1], 16;" :: "r"(dst), "l"(src) : "memory");
}
#define CP_COMMIT() asm volatile("cp.async.commit_group;" ::: "memory")
#define CP_WAITG(n) asm volatile("cp.async.wait_group %0;" :: "n"(n) : "memory")

#define LDSM4(r, a) \
    asm volatile("ldmatrix.sync.aligned.m8n8.x4.shared.b16 {%0,%1,%2,%3}, [%4];" \
                 : "=r"((r)[0]), "=r"((r)[1]), "=r"((r)[2]), "=r"((r)[3]) : "r"(a))

#define MMA16816(c, a, b0, b1) \
    asm volatile("mma.sync.aligned.m16n8k16.row.col.f32.f16.f16.f32 " \
                 "{%0,%1,%2,%3}, {%4,%5,%6,%7}, {%8,%9}, {%0,%1,%2,%3};" \
                 : "+f"((c)[0]), "+f"((c)[1]), "+f"((c)[2]), "+f"((c)[3]) \
                 : "r"((a)[0]), "r"((a)[1]), "r"((a)[2]), "r"((a)[3]), "r"(b0), "r"(b1))

// ---------------- prep ------------------------------------------------------
__global__ void k_prepz(const float* __restrict__ z) {
    __shared__ float t[32][33];
    int r0 = blockIdx.x * 32, c0 = blockIdx.y * 32;
    int b = r0 >> 11, l0 = r0 & 2047;
    int tx = threadIdx.x, ty = threadIdx.y;
    const float* zb = z + (size_t)b * CC * LLL;
#pragma unroll
    for (int j = 0; j < 4; j++)
        t[ty + j * 8][tx] = zb[(size_t)(c0 + ty + j * 8) * LLL + l0 + tx];
    __syncthreads();
#pragma unroll
    for (int j = 0; j < 4; j++) {
        int r = r0 + ty + j * 8, c = c0 + tx;
        float v = t[tx][ty + j * 8];
        g_zt[(size_t)r * CC + c] = v;
        g_Ah[(size_t)r * CC + c] = __float2half_rn(v);
    }
}

__global__ void k_prepcb(const float* __restrict__ cb) {
    int i = blockIdx.x * 256 + threadIdx.x;
    g_Bh[i] = __float2half_rn(cb[i] * 4096.0f);
    if (i == 0) g_loss = 0.0;
}

// ---------------- phase 1: fp16 HMMA GEMM, K-chunk 64, 3-stage pipe ---------
// CTA 256 thr, 8 warps (wm 0..3, wn 0..1), tile M=128 N=128.
// Stage: A 128 rows x 144B (64 fp16 + 16B pad) @ +0, B same @ +18432. 3 stages.
#define ROWB 144
#define A_ST 18432
#define STAGE_B 36864
#define SMEM_MMA (3 * STAGE_B)

__global__ __launch_bounds__(256, 2) void k_mma() {
    extern __shared__ char smem[];
    const uint32_t sb = smem_u32(smem);
    const int tid = threadIdx.x, lane = tid & 31, wid = tid >> 5;
    const int wm = wid & 3, wn = wid >> 2;
    const int m0 = blockIdx.x * 128, n0 = blockIdx.y * 128;

    // cp.async mapping: 1024 16B chunks per tile, 4 per thread
    const int crow = tid >> 3 << 2;           // not used directly; see idx below
    (void)crow;
    const __half* Ag = g_Ah + (size_t)m0 * CC;
    const __half* Bg = g_Bh + (size_t)n0 * CC;

    auto load_stage = [&](int s, int buf) {
        const uint32_t base = sb + buf * STAGE_B;
#pragma unroll
        for (int i = 0; i < 4; i++) {
            int idx = i * 256 + tid, row = idx >> 3, ch = idx & 7;
            cpa16(base + row * ROWB + ch * 16, Ag + (size_t)row * CC + s * 64 + ch * 8);
        }
#pragma unroll
        for (int i = 0; i < 4; i++) {
            int idx = i * 256 + tid, row = idx >> 3, ch = idx & 7;
            cpa16(base + A_ST + row * ROWB + ch * 16, Bg + (size_t)row * CC + s * 64 + ch * 8);
        }
    };

#pragma unroll
    for (int s = 0; s < 3; s++) { load_stage(s, s); CP_COMMIT(); }

    float acc[2][8][4];
#pragma unroll
    for (int i = 0; i < 2; i++)
#pragma unroll
        for (int j = 0; j < 8; j++)
#pragma unroll
            for (int k = 0; k < 4; k++) acc[i][j][k] = 0.f;

    const int q = lane >> 3, i8 = lane & 7;
    const uint32_t aoff = (uint32_t)((wm * 32 + i8 + (q & 1) * 8) * ROWB + (q >> 1) * 16);
    const uint32_t boff = (uint32_t)((wn * 64 + i8 + (q & 1) * 8) * ROWB + (q >> 1) * 16) + A_ST;

    for (int kc = 0; kc < 4; kc++) {
        CP_WAITG(2);
        __syncthreads();
        if (kc == 1) load_stage(3, 0);   // buf0: stage 0 fully consumed by all warps
        CP_COMMIT();
        const uint32_t base = sb + (kc % 3) * STAGE_B;
#pragma unroll
        for (int j = 0; j < 4; j++) {
            const uint32_t kb = base + j * 32;
            uint32_t a[2][4], b[4][4];
            LDSM4(a[0], kb + aoff);
            LDSM4(a[1], kb + aoff + 16 * ROWB);
#pragma unroll
            for (int bt = 0; bt < 4; bt++) LDSM4(b[bt], kb + boff + bt * 16 * ROWB);
#pragma unroll
            for (int mt = 0; mt < 2; mt++)
#pragma unroll
                for (int nf = 0; nf < 8; nf++) {
                    int bt = nf >> 1, p = nf & 1;
                    MMA16816(acc[mt][nf], a[mt], b[bt][p], b[bt][p + 2]);
                }
        }
    }
    __syncthreads();

    // epilogue: per-row top-4 of dot within this 128-col tile
    float* ep_d = (float*)smem;               // [128][32]
    int*   ep_i = (int*)(smem + 16384);       // [128][32]
#pragma unroll
    for (int mt = 0; mt < 2; mt++)
#pragma unroll
        for (int half = 0; half < 2; half++) {
            int rl = wm * 32 + mt * 16 + (lane >> 2) + half * 8;
            float tv[KEEP]; int tc[KEEP];
#pragma unroll
            for (int j = 0; j < KEEP; j++) { tv[j] = -__int_as_float(0x7f800000); tc[j] = 0; }
#pragma unroll
            for (int nf = 0; nf < 8; nf++)
#pragma unroll
                for (int par = 0; par < 2; par++) {
                    float c = acc[mt][nf][half * 2 + par];
                    if (c > tv[KEEP - 1]) {
                        int col = wn * 64 + nf * 8 + (lane & 3) * 2 + par;
                        tv[KEEP - 1] = c; tc[KEEP - 1] = col;
#pragma unroll
                        for (int j = KEEP - 1; j > 0; j--)
                            if (tv[j] > tv[j - 1]) {
                                float tf = tv[j]; tv[j] = tv[j - 1]; tv[j - 1] = tf;
                                int tu = tc[j]; tc[j] = tc[j - 1]; tc[j - 1] = tu;
                            }
                    }
                }
            int slot = rl * 32 + (wn * 4 + (lane & 3)) * 4;
#pragma unroll
            for (int j = 0; j < KEEP; j++) {
                ep_d[slot + j] = DSCALE * tv[j];
                ep_i[slot + j] = tc[j];
            }
        }
    __syncthreads();
    if (tid < 128) {
        float* pd = ep_d + tid * 32;
        int*   pi = ep_i + tid * 32;
        size_t out = (size_t)(m0 + tid) * NCAND + blockIdx.y * KEEP;
#pragma unroll
        for (int j = 0; j < KEEP; j++) {
            float bm = pd[0]; int bk = 0;
#pragma unroll 8
            for (int t = 1; t < 32; t++)
                if (pd[t] < bm) { bm = pd[t]; bk = t; }
            g_cd[out + j] = bm;
            g_ci[out + j] = n0 + pi[bk];
            pd[bk] = __int_as_float(0x7f800000);
        }
    }
}

// ---------------- phase 2: margin filter + exact fp32 rescore ---------------
__global__ void k_pick(const float* __restrict__ cb, float* __restrict__ out) {
    const int wid = threadIdx.x >> 5, lane = threadIdx.x & 31;
    const int r = blockIdx.x * 8 + wid;
    const float* cd = g_cd + (size_t)r * NCAND;
    const int*   ci = g_ci + (size_t)r * NCAND;
    float dv[8]; int iv[8];
    float mn = __int_as_float(0x7f800000);
#pragma unroll
    for (int j = 0; j < 8; j++) {
        dv[j] = cd[lane + j * 32]; iv[j] = ci[lane + j * 32];
        mn = fminf(mn, dv[j]);
    }
#pragma unroll
    for (int o = 16; o; o >>= 1) mn = fminf(mn, __shfl_xor_sync(0xffffffffu, mn, o));
    const float thr = mn + MARGIN;

    float zr[8];
    const float* zt = g_zt + (size_t)r * CC;
#pragma unroll
    for (int k = 0; k < 8; k++) zr[k] = zt[lane + k * 32];
    // per-row |z|^2: any consistent per-row value preserves the argmin
    float z2r = 0.f;
#pragma unroll
    for (int k = 0; k < 8; k++) z2r = fmaf(zr[k], zr[k], z2r);
#pragma unroll
    for (int o = 16; o; o >>= 1) z2r += __shfl_xor_sync(0xffffffffu, z2r, o);

    float best = __int_as_float(0x7f800000); int besti = 0x7fffffff;
#pragma unroll
    for (int j = 0; j < 8; j++) {
        unsigned m = __ballot_sync(0xffffffffu, dv[j] <= thr);
        while (m) {
            int src = __ffs(m) - 1; m &= m - 1;
            int n = __shfl_sync(0xffffffffu, iv[j], src);
            const float* cbn = cb + (size_t)n * CC;
            float s = 0.f;
#pragma unroll
            for (int k = 0; k < 8; k++) s = fmaf(zr[k], cbn[lane + k * 32], s);
#pragma unroll
            for (int o = 16; o; o >>= 1) s += __shfl_xor_sync(0xffffffffu, s, o);
            float dx = __fmaf_rn(-2.f, s, z2r);
            if (dx < best || (dx == best && n < besti)) { best = dx; besti = n; }
        }
    }
    if (lane == 0) { g_inds[r] = besti; out[IND_OFF + r] = (float)besti; }
}

// ---------------- z_q gather + loss -----------------------------------------
__global__ void k_zq(const float* __restrict__ z, const float* __restrict__ cb,
                     float* __restrict__ out) {
    int e = blockIdx.x * 256 + threadIdx.x;
    int l = e & 2047;
    int c = (e >> 11) & 255;
    int b = e >> 19;
    int r = (b << 11) | l;
    float v = cb[g_inds[r] * CC + c];
    out[e] = v;
    float diff = v - z[e];
    double d2 = (double)diff * (double)diff;
#pragma unroll
    for (int o = 16; o; o >>= 1) d2 += __shfl_down_sync(0xffffffffu, d2, o);
    __shared__ double ws[8];
    if ((threadIdx.x & 31) == 0) ws[threadIdx.x >> 5] = d2;
    __syncthreads();
    if (threadIdx.x == 0) {
        double s = 0.0;
#pragma unroll
        for (int w = 0; w < 8; w++) s += ws[w];
        atomicAdd(&g_loss, s);
    }
}

__global__ void k_fin(float* __restrict__ out) {
    double m = g_loss / (double)ZN;
    out[LOSS_OFF] = (float)(0.1 * m + m);
}

extern "C" void kernel_launch(void* const* d_in, const int* in_sizes, int n_in,
                              void* d_out, int out_size) {
    const float* z  = (const float*)d_in[0];
    const float* cb = (const float*)d_in[1];
    if (n_in >= 2 && in_sizes[0] == NE * CC) { z = (const float*)d_in[1]; cb = (const float*)d_in[0]; }
    float* out = (float*)d_out;

    cudaFuncSetAttribute(k_mma, cudaFuncAttributeMaxDynamicSharedMemorySize, SMEM_MMA);

    k_prepz<<<dim3(RR / 32, CC / 32), dim3(32, 8)>>>(z);
    k_prepcb<<<NE * CC / 256, 256>>>(cb);
    k_mma<<<dim3(RR / 128, NE / 128), 256, SMEM_MMA>>>();
    k_pick<<<RR / 8, 256>>>(cb, out);
    k_zq<<<ZN / 256, 256>>>(z, cb, out);
    k_fin<<<1, 1>>>(out);
}